// round 6
// baseline (speedup 1.0000x reference)
#include <cuda_runtime.h>
#include <cuda_fp16.h>

#define DK 32
#define ODIM 32
#define MAX_NODES 100002
#define MAX_N 100000
#define NPW 2            // nodes per warp
#define WPB 4            // warps per block (block = 128 threads)

// Scratch (device globals — no allocation in kernel_launch)
__device__ int g_row_ptr[MAX_NODES];
__device__ __align__(16) float g_Agg[MAX_N * DK];
// Packed per-node 128B line: halves [K0..K31 | V0..V31]
__device__ __align__(16) __half g_KV[MAX_N * 2 * DK];

// ---------------------------------------------------------------------------
// Prep kernel (fused): blocks [0, packBlocks) pack KV to fp16; the rest build
// CSR row pointers from sorted dst, 4 edges per thread via int4 loads.
// ---------------------------------------------------------------------------
__global__ __launch_bounds__(256) void prep_kernel(
    const float* __restrict__ Kf,
    const float* __restrict__ Vf,
    const int*   __restrict__ dst,
    int N, int E, int packBlocks)
{
    if ((int)blockIdx.x < packBlocks) {
        // ---- KV pack: one uint4 (8 halves) per thread ----
        const int c = blockIdx.x * 256 + threadIdx.x;      // chunk id
        if (c >= N * 8) return;
        const int node = c >> 3;
        const int part = c & 7;                            // 0-3: K, 4-7: V
        const float* sp = (part < 4 ? Kf : Vf) + (size_t)node * DK + (part & 3) * 8;
        const float4 a = *reinterpret_cast<const float4*>(sp);
        const float4 b = *reinterpret_cast<const float4*>(sp + 4);
        __half2 h0 = __floats2half2_rn(a.x, a.y);
        __half2 h1 = __floats2half2_rn(a.z, a.w);
        __half2 h2 = __floats2half2_rn(b.x, b.y);
        __half2 h3 = __floats2half2_rn(b.z, b.w);
        uint4 o;
        o.x = *reinterpret_cast<unsigned*>(&h0);
        o.y = *reinterpret_cast<unsigned*>(&h1);
        o.z = *reinterpret_cast<unsigned*>(&h2);
        o.w = *reinterpret_cast<unsigned*>(&h3);
        reinterpret_cast<uint4*>(g_KV)[c] = o;
    } else {
        // ---- Row pointers: 4 edges per thread ----
        const int t  = (blockIdx.x - packBlocks) * 256 + threadIdx.x;
        const int e0 = t * 4;
        if (e0 >= E) return;
        int ds[4];
        if (e0 + 3 < E) {
            const int4 d4 = *reinterpret_cast<const int4*>(dst + e0);
            ds[0] = d4.x; ds[1] = d4.y; ds[2] = d4.z; ds[3] = d4.w;
        } else {
            #pragma unroll
            for (int j = 0; j < 4; ++j) ds[j] = (e0 + j < E) ? dst[e0 + j] : 0;
        }
        int p = (e0 > 0) ? dst[e0 - 1] : -1;
        #pragma unroll
        for (int j = 0; j < 4; ++j) {
            const int e = e0 + j;
            if (e < E) {
                const int d = ds[j];
                for (int n = p + 1; n <= d; ++n) g_row_ptr[n] = e;
                p = d;
                if (e == E - 1)
                    for (int n = d + 1; n <= N; ++n) g_row_ptr[n] = E;
            }
        }
    }
}

// ---------------------------------------------------------------------------
// Edge kernel: warp handles NPW nodes. 8-lane groups fetch one packed KV line
// (128B) per edge with a single LDG.128 -> ONE L1 wavefront per edge.
// Lane qd in [0,8): qd<4 holds K halves 8qd..8qd+7, qd>=4 holds V halves.
// Uniform lane code: every lane converts + FMAs; K-lanes' sums form the dot.
// ---------------------------------------------------------------------------
__global__ __launch_bounds__(128, 8) void gat_edge_kernel(
    const float* __restrict__ X,
    const int*   __restrict__ src,
    int N)
{
    const unsigned FULL = 0xffffffffu;
    const int lane = threadIdx.x & 31;
    const int warp = (blockIdx.x * blockDim.x + threadIdx.x) >> 5;
    const int node0 = warp * NPW;
    if (node0 >= N) return;

    const int g  = lane >> 3;   // edge slot within a 4-edge sub-batch
    const int qd = lane & 7;
    const int kq = qd & 3;      // which 8-dim slice of q this lane dots

    #pragma unroll
    for (int ni = 0; ni < NPW; ++ni) {
        const int node = node0 + ni;
        if (node >= N) break;
        const int beg = g_row_ptr[node];
        const int end = g_row_ptr[node + 1];

        // 8 query dims for this lane's slice, prescaled by 1/DK.
        float q[8];
        {
            const float4 qa = *reinterpret_cast<const float4*>(X + (size_t)node * DK + kq * 8);
            const float4 qb = *reinterpret_cast<const float4*>(X + (size_t)node * DK + kq * 8 + 4);
            q[0] = qa.x * (1.f/DK); q[1] = qa.y * (1.f/DK);
            q[2] = qa.z * (1.f/DK); q[3] = qa.w * (1.f/DK);
            q[4] = qb.x * (1.f/DK); q[5] = qb.y * (1.f/DK);
            q[6] = qb.z * (1.f/DK); q[7] = qb.w * (1.f/DK);
        }

        float acc[8];
        #pragma unroll
        for (int j = 0; j < 8; ++j) acc[j] = 0.f;
        float lsum = 0.f;

        int base = beg;
        // Full iterations: 8 edges = 2 sub-batches of 4.
        for (; base + 8 <= end; base += 8) {
            const int sA = __ldg(&src[base + g]);
            const int sB = __ldg(&src[base + 4 + g]);
            const uint4 ha = reinterpret_cast<const uint4*>(g_KV)[(size_t)sA * 8 + qd];
            const uint4 hb = reinterpret_cast<const uint4*>(g_KV)[(size_t)sB * 8 + qd];

            float fa[8], fb[8];
            {
                float2 t;
                t = __half22float2(*reinterpret_cast<const __half2*>(&ha.x)); fa[0]=t.x; fa[1]=t.y;
                t = __half22float2(*reinterpret_cast<const __half2*>(&ha.y)); fa[2]=t.x; fa[3]=t.y;
                t = __half22float2(*reinterpret_cast<const __half2*>(&ha.z)); fa[4]=t.x; fa[5]=t.y;
                t = __half22float2(*reinterpret_cast<const __half2*>(&ha.w)); fa[6]=t.x; fa[7]=t.y;
                t = __half22float2(*reinterpret_cast<const __half2*>(&hb.x)); fb[0]=t.x; fb[1]=t.y;
                t = __half22float2(*reinterpret_cast<const __half2*>(&hb.y)); fb[2]=t.x; fb[3]=t.y;
                t = __half22float2(*reinterpret_cast<const __half2*>(&hb.z)); fb[4]=t.x; fb[5]=t.y;
                t = __half22float2(*reinterpret_cast<const __half2*>(&hb.w)); fb[6]=t.x; fb[7]=t.y;
            }

            float dA = 0.f, dB = 0.f;
            #pragma unroll
            for (int j = 0; j < 8; ++j) { dA += q[j]*fa[j]; dB += q[j]*fb[j]; }
            // Reduce within the K half (lanes qd 0-3) of each 8-lane group.
            dA += __shfl_xor_sync(FULL, dA, 1);
            dB += __shfl_xor_sync(FULL, dB, 1);
            dA += __shfl_xor_sync(FULL, dA, 2);
            dB += __shfl_xor_sync(FULL, dB, 2);
            // Broadcast group lane 0's (true) dot to all 8 lanes.
            dA = __shfl_sync(FULL, dA, 0, 8);
            dB = __shfl_sync(FULL, dB, 0, 8);

            const float pA = __expf(dA);
            const float pB = __expf(dB);
            lsum += pA + pB;
            #pragma unroll
            for (int j = 0; j < 8; ++j) acc[j] += pA*fa[j] + pB*fb[j];
        }

        // Masked tail.
        if (base < end) {
            const int eA = base + g;
            const int eB = base + 4 + g;
            const bool vA = (eA < end);
            const bool vB = (eB < end);
            const int sA = __ldg(&src[vA ? eA : beg]);
            const int sB = __ldg(&src[vB ? eB : beg]);
            const uint4 ha = reinterpret_cast<const uint4*>(g_KV)[(size_t)sA * 8 + qd];
            const uint4 hb = reinterpret_cast<const uint4*>(g_KV)[(size_t)sB * 8 + qd];

            float fa[8], fb[8];
            {
                float2 t;
                t = __half22float2(*reinterpret_cast<const __half2*>(&ha.x)); fa[0]=t.x; fa[1]=t.y;
                t = __half22float2(*reinterpret_cast<const __half2*>(&ha.y)); fa[2]=t.x; fa[3]=t.y;
                t = __half22float2(*reinterpret_cast<const __half2*>(&ha.z)); fa[4]=t.x; fa[5]=t.y;
                t = __half22float2(*reinterpret_cast<const __half2*>(&ha.w)); fa[6]=t.x; fa[7]=t.y;
                t = __half22float2(*reinterpret_cast<const __half2*>(&hb.x)); fb[0]=t.x; fb[1]=t.y;
                t = __half22float2(*reinterpret_cast<const __half2*>(&hb.y)); fb[2]=t.x; fb[3]=t.y;
                t = __half22float2(*reinterpret_cast<const __half2*>(&hb.z)); fb[4]=t.x; fb[5]=t.y;
                t = __half22float2(*reinterpret_cast<const __half2*>(&hb.w)); fb[6]=t.x; fb[7]=t.y;
            }

            float dA = 0.f, dB = 0.f;
            #pragma unroll
            for (int j = 0; j < 8; ++j) { dA += q[j]*fa[j]; dB += q[j]*fb[j]; }
            dA += __shfl_xor_sync(FULL, dA, 1);
            dB += __shfl_xor_sync(FULL, dB, 1);
            dA += __shfl_xor_sync(FULL, dA, 2);
            dB += __shfl_xor_sync(FULL, dB, 2);
            dA = __shfl_sync(FULL, dA, 0, 8);
            dB = __shfl_sync(FULL, dB, 0, 8);

            const float pA = vA ? __expf(dA) : 0.f;
            const float pB = vB ? __expf(dB) : 0.f;
            lsum += pA + pB;
            #pragma unroll
            for (int j = 0; j < 8; ++j) acc[j] += pA*fa[j] + pB*fb[j];
        }

        // Reduce across the 4 groups (lanes l, l^8, l^16, l^24 share qd).
        #pragma unroll
        for (int o = 8; o <= 16; o <<= 1) {
            #pragma unroll
            for (int j = 0; j < 8; ++j) acc[j] += __shfl_xor_sync(FULL, acc[j], o);
            lsum += __shfl_xor_sync(FULL, lsum, o);
        }
        const float inv = (lsum > 0.f) ? (1.f / lsum) : 0.f;

        // V-half lanes 4-7 (group 0) hold agg dims 8(qd-4)..8(qd-4)+7.
        if (lane >= 4 && lane < 8) {
            const int i = lane - 4;
            float4 o0, o1;
            o0.x = acc[0]*inv; o0.y = acc[1]*inv; o0.z = acc[2]*inv; o0.w = acc[3]*inv;
            o1.x = acc[4]*inv; o1.y = acc[5]*inv; o1.z = acc[6]*inv; o1.w = acc[7]*inv;
            *reinterpret_cast<float4*>(&g_Agg[(size_t)node * DK + i * 8])     = o0;
            *reinterpret_cast<float4*>(&g_Agg[(size_t)node * DK + i * 8 + 4]) = o1;
        }
    }
}

// ---------------------------------------------------------------------------
// Projection: out = Agg @ Wo + b. 64 nodes per block.
// ---------------------------------------------------------------------------
__global__ __launch_bounds__(256) void proj_kernel(
    const float* __restrict__ Wo,
    const float* __restrict__ bo,
    float* __restrict__ out,
    int N)
{
    __shared__ float4 sWoT4[ODIM][9];           // padded transposed Wo
    __shared__ __align__(16) float sAgg[64][DK];
    __shared__ float sB[ODIM];

    for (int i = threadIdx.x; i < DK * ODIM; i += 256) {
        const int d = i >> 5, c = i & 31;
        reinterpret_cast<float*>(&sWoT4[c][0])[d] = Wo[i];
    }
    if (threadIdx.x < ODIM) sB[threadIdx.x] = bo[threadIdx.x];

    const int tile = blockIdx.x * 64;
    for (int i = threadIdx.x; i < 64 * DK / 4; i += 256) {
        const int gidx = tile * (DK / 4) + i;
        float4 v = make_float4(0.f, 0.f, 0.f, 0.f);
        if (gidx < N * (DK / 4))
            v = *(reinterpret_cast<const float4*>(g_Agg) + gidx);
        *(reinterpret_cast<float4*>(&sAgg[0][0]) + i) = v;
    }
    __syncthreads();

    const int lane = threadIdx.x & 31;
    const int w    = threadIdx.x >> 5;

    float o[8];
    #pragma unroll
    for (int n = 0; n < 8; ++n) o[n] = 0.f;

    #pragma unroll
    for (int dq = 0; dq < 8; ++dq) {
        const float4 wt = sWoT4[lane][dq];
        #pragma unroll
        for (int n = 0; n < 8; ++n) {
            const float4 a = *reinterpret_cast<const float4*>(&sAgg[w * 8 + n][dq * 4]);
            o[n] += a.x * wt.x + a.y * wt.y + a.z * wt.z + a.w * wt.w;
        }
    }

    const float b = sB[lane];
    #pragma unroll
    for (int n = 0; n < 8; ++n) {
        const int node = tile + w * 8 + n;
        if (node < N)
            out[(size_t)node * ODIM + lane] = o[n] + b;
    }
}

extern "C" void kernel_launch(void* const* d_in, const int* in_sizes, int n_in,
                              void* d_out, int out_size) {
    const float* X   = (const float*)d_in[0];
    const float* K   = (const float*)d_in[1];
    const float* V   = (const float*)d_in[2];
    const float* Wo  = (const float*)d_in[3];
    const float* bo  = (const float*)d_in[4];
    const int*   src = (const int*)d_in[5];
    const int*   dst = (const int*)d_in[6];

    const int N = in_sizes[0] / DK;   // 100000
    const int E = in_sizes[5];        // 1600000

    const int packBlocks = (N * 8 + 255) / 256;          // 3125
    const int rpBlocks   = ((E + 3) / 4 + 255) / 256;    // 1563
    prep_kernel<<<packBlocks + rpBlocks, 256>>>(K, V, dst, N, E, packBlocks);

    const int warps  = (N + NPW - 1) / NPW;              // 50000
    const int blocks = (warps + WPB - 1) / WPB;          // 12500
    gat_edge_kernel<<<blocks, 32 * WPB>>>(X, src, N);

    const int pblocks = (N + 63) / 64;                   // 1563
    proj_kernel<<<pblocks, 256>>>(Wo, bo, (float*)d_out, N);
}

// round 7
// speedup vs baseline: 1.1489x; 1.1489x over previous
#include <cuda_runtime.h>

#define DK 32
#define ODIM 32
#define MAX_NODES 100002
#define WPB 4            // warps per block (block = 128 threads)

// Scratch: CSR row pointers (device global — no allocation in kernel_launch)
__device__ int g_row_ptr[MAX_NODES];

// ---------------------------------------------------------------------------
// Kernel 1: build row pointers from sorted dst. 4 edges per thread via int4.
// ---------------------------------------------------------------------------
__global__ __launch_bounds__(256) void build_row_ptr_kernel(
    const int* __restrict__ dst, int E, int N)
{
    const int t  = blockIdx.x * blockDim.x + threadIdx.x;
    const int e0 = t * 4;
    if (e0 >= E) return;

    int ds[4];
    if (e0 + 3 < E) {
        const int4 d4 = *reinterpret_cast<const int4*>(dst + e0);
        ds[0] = d4.x; ds[1] = d4.y; ds[2] = d4.z; ds[3] = d4.w;
    } else {
        #pragma unroll
        for (int j = 0; j < 4; ++j) ds[j] = (e0 + j < E) ? dst[e0 + j] : 0;
    }
    int p = (e0 > 0) ? dst[e0 - 1] : -1;
    #pragma unroll
    for (int j = 0; j < 4; ++j) {
        const int e = e0 + j;
        if (e < E) {
            const int d = ds[j];
            for (int n = p + 1; n <= d; ++n) g_row_ptr[n] = e;
            p = d;
            if (e == E - 1)
                for (int n = d + 1; n <= N; ++n) g_row_ptr[n] = E;
        }
    }
}

// ---------------------------------------------------------------------------
// Kernel 2 (fused): one warp per node. 8-lane groups fetch one K row + one V
// row per edge as single LDG.128s; src indices software-prefetched one
// iteration ahead. Epilogue: smem transpose + 32x32 projection in-warp.
// ---------------------------------------------------------------------------
__global__ __launch_bounds__(128, 11) void gat_kernel(
    const float* __restrict__ X,
    const float* __restrict__ Kf,
    const float* __restrict__ Vf,
    const float* __restrict__ Wo,
    const float* __restrict__ bo,
    const int*   __restrict__ src,
    float* __restrict__ out,
    int N)
{
    const unsigned FULL = 0xffffffffu;
    __shared__ float sWo[DK][ODIM];
    __shared__ float sBo[ODIM];
    __shared__ __align__(16) float sAgg[WPB][DK];

    // Cooperative fill (all threads, before any early-out).
    for (int i = threadIdx.x; i < DK * ODIM; i += blockDim.x)
        sWo[i / ODIM][i % ODIM] = Wo[i];
    if (threadIdx.x < ODIM) sBo[threadIdx.x] = bo[threadIdx.x];
    __syncthreads();

    const int lane = threadIdx.x & 31;
    const int wib  = threadIdx.x >> 5;
    const int node = (blockIdx.x * blockDim.x + threadIdx.x) >> 5;
    if (node >= N) return;

    const int g  = lane >> 3;   // edge slot within a 4-edge sub-batch
    const int qd = lane & 7;    // float4 dim-quad this lane covers
    const float bval = sBo[lane];

    const int beg = g_row_ptr[node];
    const int end = g_row_ptr[node + 1];

    // Query quad, prescaled by 1/DK.
    float4 q4 = *reinterpret_cast<const float4*>(X + (size_t)node * DK + qd * 4);
    q4.x *= (1.f / DK); q4.y *= (1.f / DK); q4.z *= (1.f / DK); q4.w *= (1.f / DK);

    float4 acc = make_float4(0.f, 0.f, 0.f, 0.f);
    float lsum = 0.f;

    if (end > beg) {
        const int last = end - 1;
        // Prime the src pipeline (clamped — safe while end > beg).
        int sA = __ldg(&src[min(beg + g,     last)]);
        int sB = __ldg(&src[min(beg + 4 + g, last)]);

        for (int base = beg; base < end; base += 8) {
            // Prefetch next iteration's src pair (clamped; dead on last iter).
            const int sA2 = __ldg(&src[min(base + 8  + g, last)]);
            const int sB2 = __ldg(&src[min(base + 12 + g, last)]);

            const float4 kA = *(reinterpret_cast<const float4*>(Kf + (size_t)sA * DK) + qd);
            const float4 kB = *(reinterpret_cast<const float4*>(Kf + (size_t)sB * DK) + qd);
            const float4 vA = *(reinterpret_cast<const float4*>(Vf + (size_t)sA * DK) + qd);
            const float4 vB = *(reinterpret_cast<const float4*>(Vf + (size_t)sB * DK) + qd);

            float dA = q4.x*kA.x + q4.y*kA.y + q4.z*kA.z + q4.w*kA.w;
            float dB = q4.x*kB.x + q4.y*kB.y + q4.z*kB.z + q4.w*kB.w;
            #pragma unroll
            for (int o = 1; o <= 4; o <<= 1) {
                dA += __shfl_xor_sync(FULL, dA, o);
                dB += __shfl_xor_sync(FULL, dB, o);
            }
            const bool mA = (base + g     < end);
            const bool mB = (base + 4 + g < end);
            const float pA = mA ? __expf(dA) : 0.f;
            const float pB = mB ? __expf(dB) : 0.f;
            lsum += pA + pB;
            acc.x += pA * vA.x + pB * vB.x;
            acc.y += pA * vA.y + pB * vB.y;
            acc.z += pA * vA.z + pB * vB.z;
            acc.w += pA * vA.w + pB * vB.w;

            sA = sA2; sB = sB2;
        }
    }

    // Reduce acc + lsum across the 4 edge-groups (bits 3,4 only).
    #pragma unroll
    for (int o = 8; o <= 16; o <<= 1) {
        acc.x += __shfl_xor_sync(FULL, acc.x, o);
        acc.y += __shfl_xor_sync(FULL, acc.y, o);
        acc.z += __shfl_xor_sync(FULL, acc.z, o);
        acc.w += __shfl_xor_sync(FULL, acc.w, o);
        lsum  += __shfl_xor_sync(FULL, lsum,  o);
    }
    const float inv = (lsum > 0.f) ? (1.f / lsum) : 0.f;

    // Transpose agg into smem: lanes 0..7 hold quads 0..7 of the full vector.
    __syncwarp();
    if (lane < 8)
        *reinterpret_cast<float4*>(&sAgg[wib][lane * 4]) = acc;
    __syncwarp();

    // Projection: out[node][lane] = (sum_d agg_d * Wo[d][lane]) * inv + b[lane].
    float o = 0.f;
    #pragma unroll
    for (int qq = 0; qq < 8; ++qq) {
        const float4 a = *reinterpret_cast<const float4*>(&sAgg[wib][qq * 4]);
        o += a.x * sWo[4*qq+0][lane] + a.y * sWo[4*qq+1][lane]
           + a.z * sWo[4*qq+2][lane] + a.w * sWo[4*qq+3][lane];
    }
    out[(size_t)node * ODIM + lane] = o * inv + bval;
}

extern "C" void kernel_launch(void* const* d_in, const int* in_sizes, int n_in,
                              void* d_out, int out_size) {
    const float* X   = (const float*)d_in[0];
    const float* K   = (const float*)d_in[1];
    const float* V   = (const float*)d_in[2];
    const float* Wo  = (const float*)d_in[3];
    const float* bo  = (const float*)d_in[4];
    const int*   src = (const int*)d_in[5];
    const int*   dst = (const int*)d_in[6];

    const int N = in_sizes[0] / DK;   // 100000
    const int E = in_sizes[5];        // 1600000

    const int rpThreads = (E + 3) / 4;
    build_row_ptr_kernel<<<(rpThreads + 255) / 256, 256>>>(dst, E, N);

    const int blocks = (N + WPB - 1) / WPB;    // one warp per node; 25000 blocks
    gat_kernel<<<blocks, 32 * WPB>>>(X, K, V, Wo, bo, src, (float*)d_out, N);
}

// round 8
// speedup vs baseline: 1.2324x; 1.0726x over previous
#include <cuda_runtime.h>
#include <cuda_fp16.h>

#define DK 32
#define ODIM 32
#define MAX_NODES 100002
#define MAX_N 100000
#define NPW 2            // nodes per warp
#define WPB 4            // warps per block (block = 128 threads)

// Scratch (device globals — no allocation in kernel_launch)
__device__ int g_row_ptr[MAX_NODES];
// Packed per-node 128B line of 16B chunks; chunk qd = [K quad qd | V quad qd] halves.
__device__ __align__(16) __half g_KV[MAX_N * 2 * DK];

// ---------------------------------------------------------------------------
// Prep kernel (fused): blocks [0, packBlocks) pack interleaved fp16 KV;
// remaining blocks build CSR row pointers (4 edges/thread via int4).
// ---------------------------------------------------------------------------
__global__ __launch_bounds__(256) void prep_kernel(
    const float* __restrict__ Kf,
    const float* __restrict__ Vf,
    const int*   __restrict__ dst,
    int N, int E, int packBlocks)
{
    if ((int)blockIdx.x < packBlocks) {
        // ---- KV pack: one 16B chunk per thread: [K quad | V quad] halves ----
        const int c = blockIdx.x * 256 + threadIdx.x;
        if (c >= N * 8) return;
        const int node = c >> 3;
        const int qd   = c & 7;
        const float4 kq = *reinterpret_cast<const float4*>(Kf + (size_t)node * DK + qd * 4);
        const float4 vq = *reinterpret_cast<const float4*>(Vf + (size_t)node * DK + qd * 4);
        __half2 h0 = __floats2half2_rn(kq.x, kq.y);
        __half2 h1 = __floats2half2_rn(kq.z, kq.w);
        __half2 h2 = __floats2half2_rn(vq.x, vq.y);
        __half2 h3 = __floats2half2_rn(vq.z, vq.w);
        uint4 o;
        o.x = *reinterpret_cast<unsigned*>(&h0);
        o.y = *reinterpret_cast<unsigned*>(&h1);
        o.z = *reinterpret_cast<unsigned*>(&h2);
        o.w = *reinterpret_cast<unsigned*>(&h3);
        reinterpret_cast<uint4*>(g_KV)[c] = o;
    } else {
        // ---- Row pointers: 4 edges per thread ----
        const int t  = (blockIdx.x - packBlocks) * 256 + threadIdx.x;
        const int e0 = t * 4;
        if (e0 >= E) return;
        int ds[4];
        if (e0 + 3 < E) {
            const int4 d4 = *reinterpret_cast<const int4*>(dst + e0);
            ds[0] = d4.x; ds[1] = d4.y; ds[2] = d4.z; ds[3] = d4.w;
        } else {
            #pragma unroll
            for (int j = 0; j < 4; ++j) ds[j] = (e0 + j < E) ? dst[e0 + j] : 0;
        }
        int p = (e0 > 0) ? dst[e0 - 1] : -1;
        #pragma unroll
        for (int j = 0; j < 4; ++j) {
            const int e = e0 + j;
            if (e < E) {
                const int d = ds[j];
                for (int n = p + 1; n <= d; ++n) g_row_ptr[n] = e;
                p = d;
                if (e == E - 1)
                    for (int n = d + 1; n <= N; ++n) g_row_ptr[n] = E;
            }
        }
    }
}

// ---------------------------------------------------------------------------
// Fused gat kernel: one warp per NPW nodes; 8-lane groups fetch ONE packed KV
// line per edge (one LDG.128 per lane covers its K-quad AND V-quad).
// Same lane decomposition / reductions / epilogue as the best R4 kernel.
// ---------------------------------------------------------------------------
__global__ __launch_bounds__(128, 11) void gat_kernel(
    const float* __restrict__ X,
    const float* __restrict__ Wo,
    const float* __restrict__ bo,
    const int*   __restrict__ src,
    float* __restrict__ out,
    int N)
{
    const unsigned FULL = 0xffffffffu;
    __shared__ float sWo[DK][ODIM];
    __shared__ float sBo[ODIM];
    __shared__ __align__(16) float sAgg[WPB][DK];

    for (int i = threadIdx.x; i < DK * ODIM; i += blockDim.x)
        sWo[i / ODIM][i % ODIM] = Wo[i];
    if (threadIdx.x < ODIM) sBo[threadIdx.x] = bo[threadIdx.x];
    __syncthreads();

    const int lane = threadIdx.x & 31;
    const int wib  = threadIdx.x >> 5;
    const int warp = (blockIdx.x * blockDim.x + threadIdx.x) >> 5;
    const int node0 = warp * NPW;
    if (node0 >= N) return;

    const int g  = lane >> 3;   // edge slot within a 4-edge sub-batch
    const int qd = lane & 7;    // quad (4 dims) this lane covers
    const float bval = sBo[lane];
    const uint4* __restrict__ KV4 = reinterpret_cast<const uint4*>(g_KV);

    #pragma unroll
    for (int ni = 0; ni < NPW; ++ni) {
        const int node = node0 + ni;
        if (node >= N) break;
        const int beg = g_row_ptr[node];
        const int end = g_row_ptr[node + 1];

        float4 q4 = *reinterpret_cast<const float4*>(X + (size_t)node * DK + qd * 4);
        q4.x *= (1.f / DK); q4.y *= (1.f / DK); q4.z *= (1.f / DK); q4.w *= (1.f / DK);

        float4 acc = make_float4(0.f, 0.f, 0.f, 0.f);
        float lsum = 0.f;

        int base = beg;
        // Full (unmasked) iterations: 8 edges = 2 sub-batches of 4.
        for (; base + 8 <= end; base += 8) {
            const int sA = __ldg(&src[base + g]);
            const int sB = __ldg(&src[base + 4 + g]);
            const uint4 ha = KV4[(size_t)sA * 8 + qd];
            const uint4 hb = KV4[(size_t)sB * 8 + qd];

            const float2 ka0 = __half22float2(*reinterpret_cast<const __half2*>(&ha.x));
            const float2 ka1 = __half22float2(*reinterpret_cast<const __half2*>(&ha.y));
            const float2 va0 = __half22float2(*reinterpret_cast<const __half2*>(&ha.z));
            const float2 va1 = __half22float2(*reinterpret_cast<const __half2*>(&ha.w));
            const float2 kb0 = __half22float2(*reinterpret_cast<const __half2*>(&hb.x));
            const float2 kb1 = __half22float2(*reinterpret_cast<const __half2*>(&hb.y));
            const float2 vb0 = __half22float2(*reinterpret_cast<const __half2*>(&hb.z));
            const float2 vb1 = __half22float2(*reinterpret_cast<const __half2*>(&hb.w));

            float dA = q4.x*ka0.x + q4.y*ka0.y + q4.z*ka1.x + q4.w*ka1.y;
            float dB = q4.x*kb0.x + q4.y*kb0.y + q4.z*kb1.x + q4.w*kb1.y;
            #pragma unroll
            for (int o = 1; o <= 4; o <<= 1) {
                dA += __shfl_xor_sync(FULL, dA, o);
                dB += __shfl_xor_sync(FULL, dB, o);
            }
            const float pA = __expf(dA);
            const float pB = __expf(dB);
            lsum += pA + pB;
            acc.x += pA * va0.x + pB * vb0.x;
            acc.y += pA * va0.y + pB * vb0.y;
            acc.z += pA * va1.x + pB * vb1.x;
            acc.w += pA * va1.y + pB * vb1.y;
        }

        // One masked tail iteration.
        if (base < end) {
            const int eA = base + g;
            const int eB = base + 4 + g;
            const bool mA = (eA < end);
            const bool mB = (eB < end);
            const int sA = __ldg(&src[mA ? eA : beg]);
            const int sB = __ldg(&src[mB ? eB : beg]);
            const uint4 ha = KV4[(size_t)sA * 8 + qd];
            const uint4 hb = KV4[(size_t)sB * 8 + qd];

            const float2 ka0 = __half22float2(*reinterpret_cast<const __half2*>(&ha.x));
            const float2 ka1 = __half22float2(*reinterpret_cast<const __half2*>(&ha.y));
            const float2 va0 = __half22float2(*reinterpret_cast<const __half2*>(&ha.z));
            const float2 va1 = __half22float2(*reinterpret_cast<const __half2*>(&ha.w));
            const float2 kb0 = __half22float2(*reinterpret_cast<const __half2*>(&hb.x));
            const float2 kb1 = __half22float2(*reinterpret_cast<const __half2*>(&hb.y));
            const float2 vb0 = __half22float2(*reinterpret_cast<const __half2*>(&hb.z));
            const float2 vb1 = __half22float2(*reinterpret_cast<const __half2*>(&hb.w));

            float dA = q4.x*ka0.x + q4.y*ka0.y + q4.z*ka1.x + q4.w*ka1.y;
            float dB = q4.x*kb0.x + q4.y*kb0.y + q4.z*kb1.x + q4.w*kb1.y;
            #pragma unroll
            for (int o = 1; o <= 4; o <<= 1) {
                dA += __shfl_xor_sync(FULL, dA, o);
                dB += __shfl_xor_sync(FULL, dB, o);
            }
            const float pA = mA ? __expf(dA) : 0.f;
            const float pB = mB ? __expf(dB) : 0.f;
            lsum += pA + pB;
            acc.x += pA * va0.x + pB * vb0.x;
            acc.y += pA * va0.y + pB * vb0.y;
            acc.z += pA * va1.x + pB * vb1.x;
            acc.w += pA * va1.y + pB * vb1.y;
        }

        // Reduce acc + lsum across the 4 edge-groups (bits 3,4 only).
        #pragma unroll
        for (int o = 8; o <= 16; o <<= 1) {
            acc.x += __shfl_xor_sync(FULL, acc.x, o);
            acc.y += __shfl_xor_sync(FULL, acc.y, o);
            acc.z += __shfl_xor_sync(FULL, acc.z, o);
            acc.w += __shfl_xor_sync(FULL, acc.w, o);
            lsum  += __shfl_xor_sync(FULL, lsum,  o);
        }
        const float inv = (lsum > 0.f) ? (1.f / lsum) : 0.f;

        // Transpose agg into smem: lanes 0..7 hold quads 0..7.
        __syncwarp();
        if (lane < 8)
            *reinterpret_cast<float4*>(&sAgg[wib][lane * 4]) = acc;
        __syncwarp();

        // Projection: out[node][lane] = (sum_d agg_d * Wo[d][lane]) * inv + b.
        float o = 0.f;
        #pragma unroll
        for (int qq = 0; qq < 8; ++qq) {
            const float4 a = *reinterpret_cast<const float4*>(&sAgg[wib][qq * 4]);
            o += a.x * sWo[4*qq+0][lane] + a.y * sWo[4*qq+1][lane]
               + a.z * sWo[4*qq+2][lane] + a.w * sWo[4*qq+3][lane];
        }
        out[(size_t)node * ODIM + lane] = o * inv + bval;
    }
}

extern "C" void kernel_launch(void* const* d_in, const int* in_sizes, int n_in,
                              void* d_out, int out_size) {
    const float* X   = (const float*)d_in[0];
    const float* K   = (const float*)d_in[1];
    const float* V   = (const float*)d_in[2];
    const float* Wo  = (const float*)d_in[3];
    const float* bo  = (const float*)d_in[4];
    const int*   src = (const int*)d_in[5];
    const int*   dst = (const int*)d_in[6];

    const int N = in_sizes[0] / DK;   // 100000
    const int E = in_sizes[5];        // 1600000

    const int packBlocks = (N * 8 + 255) / 256;          // 3125
    const int rpBlocks   = ((E + 3) / 4 + 255) / 256;    // 1563
    prep_kernel<<<packBlocks + rpBlocks, 256>>>(K, V, dst, N, E, packBlocks);

    const int warps  = (N + NPW - 1) / NPW;              // 50000
    const int blocks = (warps + WPB - 1) / WPB;          // 12500
    gat_kernel<<<blocks, 32 * WPB>>>(X, Wo, bo, src, (float*)d_out, N);
}